// round 13
// baseline (speedup 1.0000x reference)
#include <cuda_runtime.h>
#include <math.h>

#define NBLK  148
#define NTHR  512
#define THRESH 3.8f
#define CAP 2048

struct __align__(8) Pair { float v; int i; };
// buffer entry: {v, bitcast(i), logit0, logit1}
__device__ float4 g_bufP[CAP];
__device__ float4 g_bufN[CAP];
__device__ int  g_cntP = 0;
__device__ int  g_cntN = 0;
__device__ unsigned int g_arrive = 0;

__device__ __forceinline__ bool betterVI(float v1, int i1, float v2, int i2) {
    // jax.lax.top_k order: larger value first, ties -> lower index
    return (v1 > v2) || (v1 == v2 && i1 < i2);
}

// ---- Pair (v,i) machinery for the fallback scan ----
__device__ __forceinline__ bool better(Pair a, Pair b) { return betterVI(a.v, a.i, b.v, b.i); }
__device__ __forceinline__ void cx(Pair& x, Pair& y) {
    if (better(y, x)) { Pair t = x; x = y; y = t; }
}
__device__ __forceinline__ void pinit(Pair* t) {
#pragma unroll
    for (int k = 0; k < 8; k++) { t[k].v = -INFINITY; t[k].i = 0x7fffffff; }
}
__device__ __forceinline__ void insert8(Pair* t, float v, int i) {
    Pair c; c.v = v; c.i = i;
    if (!better(c, t[7])) return;
    t[7] = c;
#pragma unroll
    for (int k = 7; k > 0; --k) cx(t[k - 1], t[k]);
}
__device__ __forceinline__ void bitonic8(Pair* t) {
#pragma unroll
    for (int k = 0; k < 4; k++) cx(t[k], t[k + 4]);
#pragma unroll
    for (int h = 0; h < 8; h += 4) { cx(t[h], t[h + 2]); cx(t[h + 1], t[h + 3]); }
#pragma unroll
    for (int p = 0; p < 8; p += 2) cx(t[p], t[p + 1]);
}
__device__ __forceinline__ void merge_step(Pair* t, int off) {
    Pair b[8];
#pragma unroll
    for (int k = 0; k < 8; k++) {
        b[k].v = __shfl_xor_sync(0xffffffffu, t[k].v, off);
        b[k].i = __shfl_xor_sync(0xffffffffu, t[k].i, off);
    }
#pragma unroll
    for (int k = 0; k < 8; k++) {
        Pair r = b[7 - k];
        if (better(r, t[k])) t[k] = r;
    }
    bitonic8(t);
}
__device__ __forceinline__ void warp_merge1(Pair* t) {
#pragma unroll
    for (int off = 1; off < 32; off <<= 1) merge_step(t, off);
}

// ---- Quad (v,i,l0,l1) machinery for the main tail ----
struct Quad { float v; int i; float l0, l1; };
__device__ __forceinline__ void cx4(Quad& x, Quad& y) {
    if (betterVI(y.v, y.i, x.v, x.i)) { Quad t = x; x = y; y = t; }
}
__device__ __forceinline__ void qinit(Quad* t) {
#pragma unroll
    for (int k = 0; k < 8; k++) { t[k].v = -INFINITY; t[k].i = 0x7fffffff; t[k].l0 = 0.f; t[k].l1 = 0.f; }
}
__device__ __forceinline__ void qinsert8(Quad* t, Quad c) {
    if (!betterVI(c.v, c.i, t[7].v, t[7].i)) return;
    t[7] = c;
#pragma unroll
    for (int k = 7; k > 0; --k) cx4(t[k - 1], t[k]);
}
__device__ __forceinline__ void qbitonic8(Quad* t) {
#pragma unroll
    for (int k = 0; k < 4; k++) cx4(t[k], t[k + 4]);
#pragma unroll
    for (int h = 0; h < 8; h += 4) { cx4(t[h], t[h + 2]); cx4(t[h + 1], t[h + 3]); }
#pragma unroll
    for (int p = 0; p < 8; p += 2) cx4(t[p], t[p + 1]);
}
__device__ __forceinline__ void qmerge_step(Quad* t, int off) {
    Quad b[8];
#pragma unroll
    for (int k = 0; k < 8; k++) {
        b[k].v  = __shfl_xor_sync(0xffffffffu, t[k].v,  off);
        b[k].i  = __shfl_xor_sync(0xffffffffu, t[k].i,  off);
        b[k].l0 = __shfl_xor_sync(0xffffffffu, t[k].l0, off);
        b[k].l1 = __shfl_xor_sync(0xffffffffu, t[k].l1, off);
    }
#pragma unroll
    for (int k = 0; k < 8; k++) {
        Quad r = b[7 - k];
        if (betterVI(r.v, r.i, t[k].v, t[k].i)) t[k] = r;
    }
    qbitonic8(t);
}
__device__ __forceinline__ void qwarp_merge1(Quad* t) {
#pragma unroll
    for (int off = 1; off < 32; off <<= 1) qmerge_step(t, off);
}

// warp-aggregated push + cooperative logit compute for each pushed entry.
// Full warp participates. Writes the complete float4 entry (v, i, a0, a1).
__device__ __forceinline__ void warp_push_gemm(float4* buf, int* cnt, bool pred,
                                               float v, int i, int lane,
                                               const float* __restrict__ h,
                                               const float* __restrict__ W, int D) {
    unsigned m = __ballot_sync(0xffffffffu, pred);
    if (m == 0) return;
    int leader = __ffs(m) - 1;
    int base = 0;
    if (lane == leader) base = atomicAdd(cnt, __popc(m));
    base = __shfl_sync(0xffffffffu, base, leader);
    int off = base + __popc(m & ((1u << lane) - 1u));
    unsigned iter = m;
    while (iter) {
        int src = __ffs(iter) - 1; iter &= iter - 1;
        int   ii = __shfl_sync(0xffffffffu, i,   src);
        float vv = __shfl_sync(0xffffffffu, v,   src);
        int   oo = __shfl_sync(0xffffffffu, off, src);
        if (oo < CAP) {
            const float4* h4 = (const float4*)(h + (long long)ii * D);
            const float4* W4 = (const float4*)W;
            const int D4 = D >> 2;
            float a0 = 0.f, a1 = 0.f;
            for (int k = lane; k < D4; k += 32) {
                float4 x  = h4[k];
                float4 w0 = W4[2 * k];
                float4 w1 = W4[2 * k + 1];
                a0 = fmaf(x.x, w0.x, fmaf(x.y, w0.z, fmaf(x.z, w1.x, fmaf(x.w, w1.z, a0))));
                a1 = fmaf(x.x, w0.y, fmaf(x.y, w0.w, fmaf(x.z, w1.y, fmaf(x.w, w1.w, a1))));
            }
#pragma unroll
            for (int o = 16; o > 0; o >>= 1) {
                a0 += __shfl_xor_sync(0xffffffffu, a0, o);
                a1 += __shfl_xor_sync(0xffffffffu, a1, o);
            }
            if (lane == 0)
                buf[oo] = make_float4(vv, __int_as_float(ii), a0, a1);
        }
    }
}

__global__ void __launch_bounds__(NTHR)
ins_fused(const float* __restrict__ h, const float* __restrict__ A,
          const float* __restrict__ W, const float* __restrict__ b,
          const int* __restrict__ bag, float* __restrict__ out,
          int N, int D, int C, int out_size)
{
    __shared__ int  idx16[16];
    __shared__ bool isLast;

    const int tid  = threadIdx.x;
    const int lane = tid & 31, warp = tid >> 5;
    const int gid  = blockIdx.x * blockDim.x + tid;
    const int stride = gridDim.x * blockDim.x;

    int col = C - 1;
    if (bag) { int raw = bag[0]; if (raw >= 0 && raw < C) col = raw; }

    const bool fast = (C == 2 && (N & 1) == 0 && (D & 3) == 0);

    // warm L2 with W & b (helps all blocks' candidate GEMMs)
    if (blockIdx.x == 0 && warp == 15) {
        const char* wp = (const char*)W;
        long long wbytes = (long long)D * C * 4;
        for (long long o = lane * 128; o < wbytes; o += 32 * 128)
            asm volatile("prefetch.global.L2 [%0];" :: "l"(wp + o));
        if (lane == 0) asm volatile("prefetch.global.L2 [%0];" :: "l"((const char*)b));
    }

    // ---------------- phase A: threshold filter sweep + inline GEMM ----------------
    if (fast) {
        const float4* A4 = (const float4*)A;   // one float4 = rows {2j, 2j+1}
        const int M = N >> 1;
        const int trips = (M + 4 * stride - 1) / (4 * stride);  // ==1 for N=500K
        for (int t = 0; t < trips; t++) {
            int j0 = gid + t * 4 * stride;
            int j1 = j0 + stride, j2 = j0 + 2 * stride, j3 = j0 + 3 * stride;
            bool q0 = j0 < M, q1 = j1 < M, q2 = j2 < M, q3 = j3 < M;
            float4 z = make_float4(0.f, 0.f, 0.f, 0.f);
            float4 x0 = q0 ? A4[j0] : z;
            float4 x1 = q1 ? A4[j1] : z;
            float4 x2 = q2 ? A4[j2] : z;
            float4 x3 = q3 ? A4[j3] : z;

            float v00 = col ? x0.y : x0.x, v01 = col ? x0.w : x0.z;
            float v10 = col ? x1.y : x1.x, v11 = col ? x1.w : x1.z;
            float v20 = col ? x2.y : x2.x, v21 = col ? x2.w : x2.z;
            float v30 = col ? x3.y : x3.x, v31 = col ? x3.w : x3.z;

            float m01 = fmaxf(fabsf(v00), fabsf(v01));
            float m23 = fmaxf(fabsf(v10), fabsf(v11));
            float m45 = fmaxf(fabsf(v20), fabsf(v21));
            float m67 = fmaxf(fabsf(v30), fabsf(v31));
            bool any = fmaxf(fmaxf(m01, m23), fmaxf(m45, m67)) > THRESH;
            if (__ballot_sync(0xffffffffu, any)) {
                warp_push_gemm(g_bufP, &g_cntP, v00 >  THRESH,  v00, 2 * j0,     lane, h, W, D);
                warp_push_gemm(g_bufN, &g_cntN, v00 < -THRESH, -v00, 2 * j0,     lane, h, W, D);
                warp_push_gemm(g_bufP, &g_cntP, v01 >  THRESH,  v01, 2 * j0 + 1, lane, h, W, D);
                warp_push_gemm(g_bufN, &g_cntN, v01 < -THRESH, -v01, 2 * j0 + 1, lane, h, W, D);
                warp_push_gemm(g_bufP, &g_cntP, v10 >  THRESH,  v10, 2 * j1,     lane, h, W, D);
                warp_push_gemm(g_bufN, &g_cntN, v10 < -THRESH, -v10, 2 * j1,     lane, h, W, D);
                warp_push_gemm(g_bufP, &g_cntP, v11 >  THRESH,  v11, 2 * j1 + 1, lane, h, W, D);
                warp_push_gemm(g_bufN, &g_cntN, v11 < -THRESH, -v11, 2 * j1 + 1, lane, h, W, D);
                warp_push_gemm(g_bufP, &g_cntP, v20 >  THRESH,  v20, 2 * j2,     lane, h, W, D);
                warp_push_gemm(g_bufN, &g_cntN, v20 < -THRESH, -v20, 2 * j2,     lane, h, W, D);
                warp_push_gemm(g_bufP, &g_cntP, v21 >  THRESH,  v21, 2 * j2 + 1, lane, h, W, D);
                warp_push_gemm(g_bufN, &g_cntN, v21 < -THRESH, -v21, 2 * j2 + 1, lane, h, W, D);
                warp_push_gemm(g_bufP, &g_cntP, v30 >  THRESH,  v30, 2 * j3,     lane, h, W, D);
                warp_push_gemm(g_bufN, &g_cntN, v30 < -THRESH, -v30, 2 * j3,     lane, h, W, D);
                warp_push_gemm(g_bufP, &g_cntP, v31 >  THRESH,  v31, 2 * j3 + 1, lane, h, W, D);
                warp_push_gemm(g_bufN, &g_cntN, v31 < -THRESH, -v31, 2 * j3 + 1, lane, h, W, D);
            }
        }
    }
    // (non-fast layouts go straight to the exact fallback in the tail)

    // ---------------- arrival: elect last block ----------------
    __threadfence();
    __syncthreads();
    if (tid == 0) isLast = (atomicAdd(&g_arrive, 1u) == (unsigned)(gridDim.x - 1));
    __syncthreads();
    if (!isLast) return;
    __threadfence();   // acquire: all blocks' buffer writes visible

    // ---------------- tail (last block only) ----------------
    const int rawP = g_cntP, rawN = g_cntN;
    const bool ok = fast && (rawP >= 8 && rawP <= CAP && rawN >= 8 && rawN <= CAP);

    // labels: 8 ones then 8 zeros
    if (tid < 16 && tid < out_size) out[tid] = (tid < 8) ? 1.0f : 0.0f;

    if (ok) {
        // warp 0 reduces pos, warp 4 reduces neg; logits ride along as payload
        if (warp == 0 || warp == 4) {
            const float4* buf = (warp == 0) ? g_bufP : g_bufN;
            const int cnt = (warp == 0) ? rawP : rawN;
            const float b0 = b[0], b1 = b[1];
            Quad t[8]; qinit(t);
            for (int j = lane; j < cnt; j += 32) {
                float4 f = buf[j];
                Quad c; c.v = f.x; c.i = __float_as_int(f.y); c.l0 = f.z; c.l1 = f.w;
                qinsert8(t, c);
            }
            qwarp_merge1(t);
            // lane k (k<8) writes row (base + k)
            if (lane < 8) {
                int row = ((warp == 0) ? 0 : 8) + lane;
                float l0 = t[lane].l0 + b0, l1 = t[lane].l1 + b1;
                float m  = fmaxf(l0, l1);
                float e0 = __expf(l0 - m), e1 = __expf(l1 - m);
                float inv = 1.f / (e0 + e1);
                if (16 + 2 * row < out_size) out[16 + 2 * row] = e0 * inv;
                if (17 + 2 * row < out_size) out[17 + 2 * row] = e1 * inv;
            }
        }
        __syncthreads();
        if (tid == 0) { g_cntP = 0; g_cntN = 0; g_arrive = 0; }
        return;
    }

    // ---------------- exact fallback: full scan + gather GEMM ----------------
    if (warp == 0) {
        Pair t2[8]; pinit(t2);
        for (int i = lane; i < N; i += 32) {
            float v = __ldg(A + (long long)i * C + col);
            insert8(t2, v, i);
        }
        warp_merge1(t2);
        if (lane == 0) {
#pragma unroll
            for (int k = 0; k < 8; k++) idx16[k] = t2[k].i;
        }
    } else if (warp == 4) {
        Pair t2[8]; pinit(t2);
        for (int i = lane; i < N; i += 32) {
            float v = __ldg(A + (long long)i * C + col);
            insert8(t2, -v, i);
        }
        warp_merge1(t2);
        if (lane == 0) {
#pragma unroll
            for (int k = 0; k < 8; k++) idx16[8 + k] = t2[k].i;
        }
    }
    __syncthreads();
    if (tid == 0) { g_cntP = 0; g_cntN = 0; g_arrive = 0; }

    // gather GEMM + softmax (generic, one warp per row; C small)
    if (warp < 16) {
        int idx = idx16[warp];
        if (idx < 0 || idx >= N) idx = 0;
        const float* hr = h + (long long)idx * D;
        if (C == 2) {
            float a0 = 0.f, a1 = 0.f;
            for (int d = lane; d < D; d += 32) {
                float x = __ldg(hr + d);
                a0 = fmaf(x, __ldg(W + 2 * d + 0), a0);
                a1 = fmaf(x, __ldg(W + 2 * d + 1), a1);
            }
#pragma unroll
            for (int off = 16; off > 0; off >>= 1) {
                a0 += __shfl_xor_sync(0xffffffffu, a0, off);
                a1 += __shfl_xor_sync(0xffffffffu, a1, off);
            }
            if (lane == 0) {
                float l0 = a0 + b[0], l1 = a1 + b[1];
                float m  = fmaxf(l0, l1);
                float e0 = __expf(l0 - m), e1 = __expf(l1 - m);
                float inv = 1.f / (e0 + e1);
                if (16 + 2 * warp < out_size) out[16 + 2 * warp] = e0 * inv;
                if (17 + 2 * warp < out_size) out[17 + 2 * warp] = e1 * inv;
            }
        } else {
            float m = -INFINITY, sum = 0.f;
            for (int c = 0; c < C; ++c) {
                float a = 0.f;
                for (int d = lane; d < D; d += 32)
                    a = fmaf(__ldg(hr + d), __ldg(W + (long long)d * C + c), a);
#pragma unroll
                for (int off = 16; off > 0; off >>= 1)
                    a += __shfl_xor_sync(0xffffffffu, a, off);
                a += b[c];
                m = fmaxf(m, a);
            }
            for (int c = 0; c < C; ++c) {
                float a = 0.f;
                for (int d = lane; d < D; d += 32)
                    a = fmaf(__ldg(hr + d), __ldg(W + (long long)d * C + c), a);
#pragma unroll
                for (int off = 16; off > 0; off >>= 1)
                    a += __shfl_xor_sync(0xffffffffu, a, off);
                a += b[c];
                sum += __expf(a - m);
            }
            for (int c = 0; c < C; ++c) {
                float a = 0.f;
                for (int d = lane; d < D; d += 32)
                    a = fmaf(__ldg(hr + d), __ldg(W + (long long)d * C + c), a);
#pragma unroll
                for (int off = 16; off > 0; off >>= 1)
                    a += __shfl_xor_sync(0xffffffffu, a, off);
                a += b[c];
                int o = 16 + warp * C + c;
                if (lane == 0 && o < out_size) out[o] = __expf(a - m) / sum;
            }
        }
    }
}

extern "C" void kernel_launch(void* const* d_in, const int* in_sizes, int n_in,
                              void* d_out, int out_size)
{
    // Identify inputs by element count:
    //   h: N*D (largest), A: N*C (2nd), W: D*C, b: C, bag: 1 (optional)
    int ih = -1, ia = -1, iw = -1, ib = -1, ibag = -1;
    long long best1 = -1, best2 = -1;
    for (int k = 0; k < n_in; k++) {
        long long sz = in_sizes[k];
        if (sz > best1) { best2 = best1; ia = ih; best1 = sz; ih = k; }
        else if (sz > best2) { best2 = sz; ia = k; }
    }
    long long wbest = -1, bbest = -1;
    for (int k = 0; k < n_in; k++) {
        if (k == ih || k == ia) continue;
        long long sz = in_sizes[k];
        if (sz == 1 && ibag < 0) { ibag = k; continue; }
        if (sz > wbest) { bbest = wbest; ib = iw; wbest = sz; iw = k; }
        else if (sz > bbest) { bbest = sz; ib = k; }
    }

    const float* h   = (const float*)d_in[ih];
    const float* A   = (const float*)d_in[ia];
    const float* W   = (const float*)d_in[iw];
    const float* b   = (const float*)d_in[ib];
    const int*   bag = (ibag >= 0) ? (const int*)d_in[ibag] : nullptr;

    int C = in_sizes[ib];
    int D = in_sizes[iw] / C;
    int N = (int)((long long)in_sizes[ih] / D);

    ins_fused<<<NBLK, NTHR>>>(h, A, W, b, bag, (float*)d_out, N, D, C, out_size);
}

// round 14
// speedup vs baseline: 1.1404x; 1.1404x over previous
#include <cuda_runtime.h>
#include <math.h>

#define NBLK  256
#define NTHR  256
#define THRESH 3.8f
#define CAP 4096

struct __align__(8) Pair { float v; int i; };

__device__ Pair g_bufP[CAP];
__device__ Pair g_bufN[CAP];
__device__ int  g_cntP = 0;
__device__ int  g_cntN = 0;
__device__ unsigned int g_arrive = 0;

__device__ __forceinline__ bool better(Pair a, Pair b) {
    // jax.lax.top_k order: larger value first, ties -> lower index
    return (a.v > b.v) || (a.v == b.v && a.i < b.i);
}

__device__ __forceinline__ void cx(Pair& x, Pair& y) {
    if (better(y, x)) { Pair t = x; x = y; y = t; }
}

__device__ __forceinline__ void pinit(Pair* t) {
#pragma unroll
    for (int k = 0; k < 8; k++) { t[k].v = -INFINITY; t[k].i = 0x7fffffff; }
}

__device__ __forceinline__ void insert8(Pair* t, float v, int i) {
    Pair c; c.v = v; c.i = i;
    if (!better(c, t[7])) return;
    t[7] = c;
#pragma unroll
    for (int k = 7; k > 0; --k) cx(t[k - 1], t[k]);
}

// sort a bitonic 8-seq into desc order: static 3-stage network
__device__ __forceinline__ void bitonic8(Pair* t) {
#pragma unroll
    for (int k = 0; k < 4; k++) cx(t[k], t[k + 4]);
#pragma unroll
    for (int h = 0; h < 8; h += 4) { cx(t[h], t[h + 2]); cx(t[h + 1], t[h + 3]); }
#pragma unroll
    for (int p = 0; p < 8; p += 2) cx(t[p], t[p + 1]);
}

// Batcher halver merge round with xor partner lane
__device__ __forceinline__ void merge_step(Pair* t, int off) {
    Pair b[8];
#pragma unroll
    for (int k = 0; k < 8; k++) {
        b[k].v = __shfl_xor_sync(0xffffffffu, t[k].v, off);
        b[k].i = __shfl_xor_sync(0xffffffffu, t[k].i, off);
    }
#pragma unroll
    for (int k = 0; k < 8; k++) {
        Pair r = b[7 - k];
        if (better(r, t[k])) t[k] = r;
    }
    bitonic8(t);
}

__device__ __forceinline__ void warp_merge1(Pair* t) {
#pragma unroll
    for (int off = 1; off < 32; off <<= 1) merge_step(t, off);
}

// warp-aggregated append (full warp participates); pushing thread also
// prefetches its h row into L2 so the tail GEMM avoids cold DRAM.
__device__ __forceinline__ void warp_push(Pair* buf, int* cnt, bool pred,
                                          float v, int i, int lane,
                                          const float* __restrict__ h, int D) {
    unsigned m = __ballot_sync(0xffffffffu, pred);
    if (m == 0) return;
    int leader = __ffs(m) - 1;
    int base = 0;
    if (lane == leader) base = atomicAdd(cnt, __popc(m));
    base = __shfl_sync(0xffffffffu, base, leader);
    if (pred) {
        int off = base + __popc(m & ((1u << lane) - 1u));
        if (off < CAP) { buf[off].v = v; buf[off].i = i; }
        const char* hp = (const char*)(h + (long long)i * D);
        int rowbytes = D * 4;
        for (int o = 0; o < rowbytes; o += 128)
            asm volatile("prefetch.global.L2 [%0];" :: "l"(hp + o));
    }
}

__global__ void __launch_bounds__(NTHR)
ins_fused(const float* __restrict__ h, const float* __restrict__ A,
          const float* __restrict__ W, const float* __restrict__ b,
          const int* __restrict__ bag, float* __restrict__ out,
          int N, int D, int C, int out_size)
{
    __shared__ int  idx16[16];
    __shared__ bool isLast;

    const int tid  = threadIdx.x;
    const int lane = tid & 31, warp = tid >> 5;
    const int gid  = blockIdx.x * blockDim.x + tid;
    const int stride = gridDim.x * blockDim.x;

    int col = C - 1;
    if (bag) { int raw = bag[0]; if (raw >= 0 && raw < C) col = raw; }

    // warm L2 with W & b for the tail
    if (blockIdx.x == 0 && warp == 7) {
        const char* wp = (const char*)W;
        long long wbytes = (long long)D * C * 4;
        for (long long o = lane * 128; o < wbytes; o += 32 * 128)
            asm volatile("prefetch.global.L2 [%0];" :: "l"(wp + o));
        if (lane == 0) asm volatile("prefetch.global.L2 [%0];" :: "l"((const char*)b));
    }

    // ---------------- phase A: threshold filter sweep ----------------
    if (C == 2 && ((N & 1) == 0)) {
        const float4* A4 = (const float4*)A;   // one float4 = rows {2j, 2j+1}
        const int M = N >> 1;
        const int trips = (M + 4 * stride - 1) / (4 * stride);
        for (int t = 0; t < trips; t++) {
            int j0 = gid + t * 4 * stride;
            int j1 = j0 + stride, j2 = j0 + 2 * stride, j3 = j0 + 3 * stride;
            bool q0 = j0 < M, q1 = j1 < M, q2 = j2 < M, q3 = j3 < M;
            float4 z = make_float4(0.f, 0.f, 0.f, 0.f);
            float4 x0 = q0 ? A4[j0] : z;
            float4 x1 = q1 ? A4[j1] : z;
            float4 x2 = q2 ? A4[j2] : z;
            float4 x3 = q3 ? A4[j3] : z;

            float v00 = col ? x0.y : x0.x, v01 = col ? x0.w : x0.z;
            float v10 = col ? x1.y : x1.x, v11 = col ? x1.w : x1.z;
            float v20 = col ? x2.y : x2.x, v21 = col ? x2.w : x2.z;
            float v30 = col ? x3.y : x3.x, v31 = col ? x3.w : x3.z;

            // one cheap ballot: does anyone in the warp have a candidate?
            float m01 = fmaxf(fabsf(v00), fabsf(v01));
            float m23 = fmaxf(fabsf(v10), fabsf(v11));
            float m45 = fmaxf(fabsf(v20), fabsf(v21));
            float m67 = fmaxf(fabsf(v30), fabsf(v31));
            bool any = fmaxf(fmaxf(m01, m23), fmaxf(m45, m67)) > THRESH;
            if (__ballot_sync(0xffffffffu, any)) {
                warp_push(g_bufP, &g_cntP, v00 >  THRESH,  v00, 2 * j0,     lane, h, D);
                warp_push(g_bufN, &g_cntN, v00 < -THRESH, -v00, 2 * j0,     lane, h, D);
                warp_push(g_bufP, &g_cntP, v01 >  THRESH,  v01, 2 * j0 + 1, lane, h, D);
                warp_push(g_bufN, &g_cntN, v01 < -THRESH, -v01, 2 * j0 + 1, lane, h, D);
                warp_push(g_bufP, &g_cntP, v10 >  THRESH,  v10, 2 * j1,     lane, h, D);
                warp_push(g_bufN, &g_cntN, v10 < -THRESH, -v10, 2 * j1,     lane, h, D);
                warp_push(g_bufP, &g_cntP, v11 >  THRESH,  v11, 2 * j1 + 1, lane, h, D);
                warp_push(g_bufN, &g_cntN, v11 < -THRESH, -v11, 2 * j1 + 1, lane, h, D);
                warp_push(g_bufP, &g_cntP, v20 >  THRESH,  v20, 2 * j2,     lane, h, D);
                warp_push(g_bufN, &g_cntN, v20 < -THRESH, -v20, 2 * j2,     lane, h, D);
                warp_push(g_bufP, &g_cntP, v21 >  THRESH,  v21, 2 * j2 + 1, lane, h, D);
                warp_push(g_bufN, &g_cntN, v21 < -THRESH, -v21, 2 * j2 + 1, lane, h, D);
                warp_push(g_bufP, &g_cntP, v30 >  THRESH,  v30, 2 * j3,     lane, h, D);
                warp_push(g_bufN, &g_cntN, v30 < -THRESH, -v30, 2 * j3,     lane, h, D);
                warp_push(g_bufP, &g_cntP, v31 >  THRESH,  v31, 2 * j3 + 1, lane, h, D);
                warp_push(g_bufN, &g_cntN, v31 < -THRESH, -v31, 2 * j3 + 1, lane, h, D);
            }
        }
    } else {
        const int trips = (N + stride - 1) / stride;
        for (int t = 0; t < trips; t++) {
            int i = gid + t * stride;
            bool q = i < N;
            float v = q ? __ldg(A + (long long)i * C + col) : 0.f;
            warp_push(g_bufP, &g_cntP, q && v >  THRESH,  v, i, lane, h, D);
            warp_push(g_bufN, &g_cntN, q && v < -THRESH, -v, i, lane, h, D);
        }
    }

    // ---------------- arrival: elect last block ----------------
    __threadfence();
    __syncthreads();
    if (tid == 0) isLast = (atomicAdd(&g_arrive, 1u) == (unsigned)(gridDim.x - 1));
    __syncthreads();
    if (!isLast) return;
    __threadfence();   // acquire: all blocks' buffer writes visible

    // ---------------- tail (last block only) ----------------
    // overlap counter read with speculative buffer loads (both L2)
    const int rawP = g_cntP, rawN = g_cntN;
    const bool ok = (rawP >= 8 && rawP <= CAP && rawN >= 8 && rawN <= CAP);

    if (ok) {
        // single-level: warp 0 reduces pos, warp 4 reduces neg (~36 entries)
        if (warp == 0 || warp == 4) {
            const Pair* buf = (warp == 0) ? g_bufP : g_bufN;
            const int cnt = (warp == 0) ? rawP : rawN;
            // speculative loads (within CAP, masked after) — issue in parallel
            Pair e0 = buf[lane];
            Pair e1 = buf[lane + 32];
            Pair e2 = buf[lane + 64];
            Pair t[8]; pinit(t);
            if (lane      < cnt) insert8(t, e0.v, e0.i);
            if (lane + 32 < cnt) insert8(t, e1.v, e1.i);
            if (lane + 64 < cnt) insert8(t, e2.v, e2.i);
            for (int j = lane + 96; j < cnt; j += 32) insert8(t, buf[j].v, buf[j].i);
            warp_merge1(t);
            if (lane == 0) {
#pragma unroll
                for (int k = 0; k < 8; k++) idx16[((warp == 0) ? 0 : 8) + k] = t[k].i;
            }
        }
    } else {
        // fallback: exact full scan, warp 0 = pos, warp 4 = neg
        if (warp == 0) {
            Pair t2[8]; pinit(t2);
            for (int i = lane; i < N; i += 32) {
                float v = __ldg(A + (long long)i * C + col);
                insert8(t2, v, i);
            }
            warp_merge1(t2);
            if (lane == 0) {
#pragma unroll
                for (int k = 0; k < 8; k++) idx16[k] = t2[k].i;
            }
        } else if (warp == 4) {
            Pair t2[8]; pinit(t2);
            for (int i = lane; i < N; i += 32) {
                float v = __ldg(A + (long long)i * C + col);
                insert8(t2, -v, i);
            }
            warp_merge1(t2);
            if (lane == 0) {
#pragma unroll
                for (int k = 0; k < 8; k++) idx16[8 + k] = t2[k].i;
            }
        }
    }
    __syncthreads();
    if (tid == 0) { g_cntP = 0; g_cntN = 0; g_arrive = 0; }  // reset for replay

    // labels: 8 ones then 8 zeros
    if (tid < 16 && tid < out_size) out[tid] = (tid < 8) ? 1.0f : 0.0f;

    // ---------------- GEMM + softmax: half-warp per row ----------------
    if (C == 2 && (D & 7) == 0) {
        const int grp = tid >> 4;        // 0..15 -> output row
        const int gl  = tid & 15;
        int idx = idx16[grp];
        if (idx < 0 || idx >= N) idx = 0;
        const float4* h4 = (const float4*)(h + (long long)idx * D);
        const float4* W4 = (const float4*)W;
        const int D4 = D >> 2;
        float a0 = 0.f, a1 = 0.f;
#pragma unroll 8
        for (int k = gl; k < D4; k += 16) {
            float4 x  = h4[k];
            float4 w0 = W4[2 * k];
            float4 w1 = W4[2 * k + 1];
            a0 = fmaf(x.x, w0.x, fmaf(x.y, w0.z, fmaf(x.z, w1.x, fmaf(x.w, w1.z, a0))));
            a1 = fmaf(x.x, w0.y, fmaf(x.y, w0.w, fmaf(x.z, w1.y, fmaf(x.w, w1.w, a1))));
        }
#pragma unroll
        for (int off = 8; off > 0; off >>= 1) {
            a0 += __shfl_xor_sync(0xffffffffu, a0, off);
            a1 += __shfl_xor_sync(0xffffffffu, a1, off);
        }
        if (gl == 0) {
            float l0 = a0 + b[0], l1 = a1 + b[1];
            float m  = fmaxf(l0, l1);
            float e0 = __expf(l0 - m), e1 = __expf(l1 - m);
            float inv = 1.f / (e0 + e1);
            if (16 + 2 * grp < out_size) out[16 + 2 * grp] = e0 * inv;
            if (17 + 2 * grp < out_size) out[17 + 2 * grp] = e1 * inv;
        }
    } else {
        // generic scalar fallback: one warp per 2 rows
        for (int row = warp; row < 16; row += 8) {
            int idx = idx16[row];
            if (idx < 0 || idx >= N) idx = 0;
            const float* hr = h + (long long)idx * D;
            float m = -INFINITY, sum = 0.f;
            for (int c = 0; c < C; ++c) {
                float a = 0.f;
                for (int d = lane; d < D; d += 32)
                    a = fmaf(__ldg(hr + d), __ldg(W + (long long)d * C + c), a);
#pragma unroll
                for (int off = 16; off > 0; off >>= 1)
                    a += __shfl_xor_sync(0xffffffffu, a, off);
                a += b[c];
                m = fmaxf(m, a);
            }
            for (int c = 0; c < C; ++c) {
                float a = 0.f;
                for (int d = lane; d < D; d += 32)
                    a = fmaf(__ldg(hr + d), __ldg(W + (long long)d * C + c), a);
#pragma unroll
                for (int off = 16; off > 0; off >>= 1)
                    a += __shfl_xor_sync(0xffffffffu, a, off);
                a += b[c];
                sum += __expf(a - m);
            }
            for (int c = 0; c < C; ++c) {
                float a = 0.f;
                for (int d = lane; d < D; d += 32)
                    a = fmaf(__ldg(hr + d), __ldg(W + (long long)d * C + c), a);
#pragma unroll
                for (int off = 16; off > 0; off >>= 1)
                    a += __shfl_xor_sync(0xffffffffu, a, off);
                a += b[c];
                int o = 16 + row * C + c;
                if (lane == 0 && o < out_size) out[o] = __expf(a - m) / sum;
            }
        }
    }
}

extern "C" void kernel_launch(void* const* d_in, const int* in_sizes, int n_in,
                              void* d_out, int out_size)
{
    // Identify inputs by element count:
    //   h: N*D (largest), A: N*C (2nd), W: D*C, b: C, bag: 1 (optional)
    int ih = -1, ia = -1, iw = -1, ib = -1, ibag = -1;
    long long best1 = -1, best2 = -1;
    for (int k = 0; k < n_in; k++) {
        long long sz = in_sizes[k];
        if (sz > best1) { best2 = best1; ia = ih; best1 = sz; ih = k; }
        else if (sz > best2) { best2 = sz; ia = k; }
    }
    long long wbest = -1, bbest = -1;
    for (int k = 0; k < n_in; k++) {
        if (k == ih || k == ia) continue;
        long long sz = in_sizes[k];
        if (sz == 1 && ibag < 0) { ibag = k; continue; }
        if (sz > wbest) { bbest = wbest; ib = iw; wbest = sz; iw = k; }
        else if (sz > bbest) { bbest = sz; ib = k; }
    }

    const float* h   = (const float*)d_in[ih];
    const float* A   = (const float*)d_in[ia];
    const float* W   = (const float*)d_in[iw];
    const float* b   = (const float*)d_in[ib];
    const int*   bag = (ibag >= 0) ? (const int*)d_in[ibag] : nullptr;

    int C = in_sizes[ib];
    int D = in_sizes[iw] / C;
    int N = (int)((long long)in_sizes[ih] / D);

    ins_fused<<<NBLK, NTHR>>>(h, A, W, b, bag, (float*)d_out, N, D, C, out_size);
}